// round 17
// baseline (speedup 1.0000x reference)
#include <cuda_runtime.h>
#include <cuda_bf16.h>

// MultiHeadSpMM: out[r, h*D+d] = sum_{e: row[e]==r} attention[e,h] * h[col[e],h,d]
// N=100000, E=1600000, H=4, D=8 (H*D == 32). row[] is sorted.
//
// R17: R15 skeleton + WARP-PRIVATE smem staging of col/att.
//   The measured bound is the per-iteration chain col-LDG(L2,~240cy) ->
//   hfeat-LDG(~240cy). Each warp stages its 4 rows' contiguous edge range
//   (col pre-scaled+clamped, att as float4) into its own smem slab with all
//   32 lanes convergent+coalesced, then the divergent 8-lane groups read
//   col/att via LDS (29cy). Exposed chain ~halves. __syncwarp only — the
//   chunk loop is warp-uniform (bounds from row_ptr[4w], row_ptr[4w+4]);
//   no block barriers, no cross-warp imbalance.

#define MAX_NODES (1 << 21)
#define CHUNK 128               // staged edges per warp-chunk
#define THREADS 64              // 2 warps per block

__device__ int g_row_ptr[MAX_NODES + 1];

__global__ void build_row_ptr_kernel(const int* __restrict__ row, int E, int N) {
    int e = blockIdx.x * blockDim.x + threadIdx.x;
    if (e >= E) return;
    int r = row[e];
    if (r < 0) r = 0;
    if (r >= N) r = N - 1;
    int prev;
    if (e == 0) {
        prev = -1;
    } else {
        prev = row[e - 1];
        if (prev < 0) prev = 0;
        if (prev >= N) prev = N - 1;
    }
    for (int i = prev + 1; i <= r; ++i) g_row_ptr[i] = e;
    if (e == E - 1) {
        for (int i = r + 1; i <= N; ++i) g_row_ptr[i] = E;
    }
}

__global__ __launch_bounds__(THREADS) void spmm_warpstage_kernel(
    const int* __restrict__ col,
    const float* __restrict__ att,   // (E, 4)
    const float* __restrict__ hfeat, // (N, 32)
    float* __restrict__ out,         // (N, 32)
    int N)
{
    __shared__ int    s_col[2][CHUNK];      // pre-scaled node offsets (c*32)
    __shared__ float4 s_att[2][CHUNK];      // att[e][0..3]

    const int tid  = threadIdx.x;
    const int wib  = tid >> 5;              // warp-in-block (0..1)
    const int lane = tid & 31;
    const int warp = (blockIdx.x * THREADS + tid) >> 5;

    const int r0 = warp * 4;
    if (r0 >= N) return;                    // warp-uniform exit

    const int g  = lane >> 3;               // group -> row r0+g
    const int q  = lane & 7;                // feature quarter
    const int hd = q >> 1;                  // head
    const int r  = r0 + g;
    const bool row_ok = (r < N);

    const int rbeg = row_ok ? g_row_ptr[r] : 0;
    const int rend = row_ok ? g_row_ptr[r + 1] : 0;

    const int ebeg = g_row_ptr[r0];
    const int eend = g_row_ptr[min(r0 + 4, N)];
    const int nmax = N - 1;

    int*    scol = s_col[wib];
    float*  satt = (float*)s_att[wib];

    float4 acc = make_float4(0.f, 0.f, 0.f, 0.f);

    for (int cb = ebeg; cb < eend; cb += CHUNK) {      // warp-uniform loop
        const int n = min(CHUNK, eend - cb);

        // ---- Stage: 32 lanes, convergent, coalesced ----
        for (int i = lane; i < n; i += 32) {
            int c = __ldg(&col[cb + i]);
            c = min(max(c, 0), nmax);
            scol[i] = c * 32;
            ((float4*)satt)[i] = __ldg((const float4*)(att + (cb + i) * 4));
        }
        __syncwarp();

        // ---- Compute: divergent 8-lane groups, col/att from smem ----
        int lo = max(rbeg, cb) - cb;
        int hi = min(rend, cb + n) - cb;    // row_ok=false -> hi<=0, skipped

        int j = lo;
        for (; j + 3 < hi; j += 4) {
            int c0 = scol[j];
            int c1 = scol[j + 1];
            int c2 = scol[j + 2];
            int c3 = scol[j + 3];

            float a0 = satt[(j    ) * 4 + hd];
            float a1 = satt[(j + 1) * 4 + hd];
            float a2 = satt[(j + 2) * 4 + hd];
            float a3 = satt[(j + 3) * 4 + hd];

            float4 h0 = __ldg((const float4*)(hfeat + c0 + q * 4));
            float4 h1 = __ldg((const float4*)(hfeat + c1 + q * 4));
            float4 h2 = __ldg((const float4*)(hfeat + c2 + q * 4));
            float4 h3 = __ldg((const float4*)(hfeat + c3 + q * 4));

            acc.x = fmaf(a0, h0.x, acc.x);
            acc.y = fmaf(a0, h0.y, acc.y);
            acc.z = fmaf(a0, h0.z, acc.z);
            acc.w = fmaf(a0, h0.w, acc.w);
            acc.x = fmaf(a1, h1.x, acc.x);
            acc.y = fmaf(a1, h1.y, acc.y);
            acc.z = fmaf(a1, h1.z, acc.z);
            acc.w = fmaf(a1, h1.w, acc.w);
            acc.x = fmaf(a2, h2.x, acc.x);
            acc.y = fmaf(a2, h2.y, acc.y);
            acc.z = fmaf(a2, h2.z, acc.z);
            acc.w = fmaf(a2, h2.w, acc.w);
            acc.x = fmaf(a3, h3.x, acc.x);
            acc.y = fmaf(a3, h3.y, acc.y);
            acc.z = fmaf(a3, h3.z, acc.z);
            acc.w = fmaf(a3, h3.w, acc.w);
        }
        for (; j < hi; ++j) {
            int c = scol[j];
            float a = satt[j * 4 + hd];
            float4 h0 = __ldg((const float4*)(hfeat + c + q * 4));
            acc.x = fmaf(a, h0.x, acc.x);
            acc.y = fmaf(a, h0.y, acc.y);
            acc.z = fmaf(a, h0.z, acc.z);
            acc.w = fmaf(a, h0.w, acc.w);
        }
        __syncwarp();
    }

    if (row_ok) {
        ((float4*)out)[r * 8 + q] = acc;    // zeros for empty rows
    }
}

extern "C" void kernel_launch(void* const* d_in, const int* in_sizes, int n_in,
                              void* d_out, int out_size) {
    const int*   row  = (const int*)  d_in[0];
    const int*   col  = (const int*)  d_in[1];
    const float* att  = (const float*)d_in[2];
    const float* hft  = (const float*)d_in[3];
    float*       out  = (float*)      d_out;

    int E = in_sizes[0];
    int N = in_sizes[3] / 32;  // h is (N, 4, 8)

    {
        int threads = 256;
        int blocks = (E + threads - 1) / threads;
        build_row_ptr_kernel<<<blocks, threads>>>(row, E, N);
    }
    {
        int rows_per_block = (THREADS / 32) * 4;   // 8
        int blocks = (N + rows_per_block - 1) / rows_per_block;
        spmm_warpstage_kernel<<<blocks, THREADS>>>(col, att, hft, out, N);
    }
}